// round 4
// baseline (speedup 1.0000x reference)
#include <cuda_runtime.h>
#include <cuda_fp16.h>
#include <cstdint>

// ---------------------------------------------------------------------------
// Fused per-pixel MLP discriminator + BCE mean (fp16 tensor-core version).
//   x[4,19,256,512] -> 1x1 convs 19->64->128->256->512->1 (leaky 0.2) -> BCE mean
// CTA = 128 pixels, 512 threads (16 warps = 4 M-groups x 4 N-slices).
// Weights pre-packed fp16 in MMA-fragment order, streamed GMEM->SMEM via
// cp.async in K=32 chunks (4-slot ring, prefetch depth 3). Activations fp16
// in SMEM. Layer4+5 fused in the epilogue (h4 never materialized).
// R4: f16-accumulator HMMA (promote to f32 every k=32) + single barrier/chunk.
// ---------------------------------------------------------------------------

#define HW_   (256 * 512)
#define NPIX  (4 * HW_)
#define BM    128
#define LEAK  0.2f

#define NCHUNKS    23          // L1:1  L2:2  L3:4  L4:16 (2 N-halves x 8 K-chunks)
#define SLOT_BYTES 16384       // max chunk = 256 cols * 32 k * 2B

// Packed fp16 weights, chunk-major. Within a chunk (N_ext cols x 32 k):
//   elem[(col*4 + tq)*8 + kc*4 + h*2 + j] = W[col][kc*16 + tq*2 + 8*h + j]
// so one LDS.128 per (col-octet thread, chunk) yields both k16-step fragments.
__device__ __align__(16) __half g_Wpk[174080];   // 2048 + 8192 + 32768 + 131072
__device__ double g_acc;

__global__ void prep_kernel(const float* __restrict__ W1, const float* __restrict__ W2,
                            const float* __restrict__ W3, const float* __restrict__ W4) {
    const int i = blockIdx.x * blockDim.x + threadIdx.x;
    if (i == 0) g_acc = 0.0;

    if (i < 64 * 32) {                    // L1: [64][19] pad K->32, chunk 0
        const int n = i >> 5, k = i & 31;
        const float v = (k < 19) ? W1[n * 19 + k] : 0.f;
        const int kc = k >> 4, r = k & 15, h = r >> 3, tq = (r & 7) >> 1, j = r & 1;
        g_Wpk[(n * 4 + tq) * 8 + kc * 4 + h * 2 + j] = __float2half_rn(v);
    }
    if (i < 128 * 64) {                   // L2: chunks 1..2
        const int n = i >> 6, k = i & 63;
        const int ch = k >> 5, kl = k & 31;
        const int kc = kl >> 4, r = kl & 15, h = r >> 3, tq = (r & 7) >> 1, j = r & 1;
        g_Wpk[2048 + ch * 4096 + (n * 4 + tq) * 8 + kc * 4 + h * 2 + j] = __float2half_rn(W2[i]);
    }
    if (i < 256 * 128) {                  // L3: chunks 3..6
        const int n = i >> 7, k = i & 127;
        const int ch = k >> 5, kl = k & 31;
        const int kc = kl >> 4, r = kl & 15, h = r >> 3, tq = (r & 7) >> 1, j = r & 1;
        g_Wpk[10240 + ch * 8192 + (n * 4 + tq) * 8 + kc * 4 + h * 2 + j] = __float2half_rn(W3[i]);
    }
    if (i < 512 * 256) {                  // L4: chunks 7..22 = [half][kchunk]
        const int n = i >> 8, k = i & 255;
        const int half = n >> 8, cl = n & 255;
        const int c8 = k >> 5, kl = k & 31;
        const int kc = kl >> 4, r = kl & 15, h = r >> 3, tq = (r & 7) >> 1, j = r & 1;
        g_Wpk[43008 + (half * 8 + c8) * 8192 + (cl * 4 + tq) * 8 + kc * 4 + h * 2 + j] =
            __float2half_rn(W4[i]);
    }
}

__device__ __forceinline__ float leaky(float v) { return v >= 0.f ? v : LEAK * v; }

// f16-accumulator HMMA: D/C are 2x b32 (4 halves).
__device__ __forceinline__ void mma_f16acc(uint32_t& d0, uint32_t& d1,
                                           const uint32_t* a, uint32_t b0, uint32_t b1) {
    asm volatile(
        "mma.sync.aligned.m16n8k16.row.col.f16.f16.f16.f16 "
        "{%0,%1},{%2,%3,%4,%5},{%6,%7},{%0,%1};\n"
        : "+r"(d0), "+r"(d1)
        : "r"(a[0]), "r"(a[1]), "r"(a[2]), "r"(a[3]), "r"(b0), "r"(b1));
}

__device__ __forceinline__ void cp_async16(void* dst, const void* src) {
    const uint32_t d = (uint32_t)__cvta_generic_to_shared(dst);
    asm volatile("cp.async.cg.shared.global [%0], [%1], 16;\n" :: "r"(d), "l"(src) : "memory");
}
__device__ __forceinline__ void cp_commit() {
    asm volatile("cp.async.commit_group;\n" ::: "memory");
}
template <int N> __device__ __forceinline__ void cp_wait() {
    asm volatile("cp.async.wait_group %0;\n" :: "n"(N) : "memory");
}

// Issue the cp.async copies for chunk c into its ring slot; ALWAYS commits a
// group (possibly empty) so wait_group arithmetic stays uniform at the tail.
__device__ __forceinline__ void stage_chunk(int c, char* ring, int tid) {
    if (c < NCHUNKS) {
        int base_e, bytes;
        if (c == 0)      { base_e = 0;                   bytes = 4096;  }
        else if (c < 3)  { base_e = 2048  + (c - 1) * 4096; bytes = 8192;  }
        else if (c < 7)  { base_e = 10240 + (c - 3) * 8192; bytes = 16384; }
        else             { base_e = 43008 + (c - 7) * 8192; bytes = 16384; }
        char* dst = ring + (c & 3) * SLOT_BYTES;
        const char* src = (const char*)g_Wpk + base_e * 2;
        for (int off = tid * 16; off < bytes; off += 512 * 16)
            cp_async16(dst + off, src + off);
    }
    cp_commit();
}

// One GEMM pass over KP reduction dims (KP/32 streamed chunks), NW cols/warp.
// Warp owns M rows [wm*32, +32) as two m16 tiles. Per-chunk: f16-acc HMMA pair
// (k=32) then promote into f32 accumulators. If FUSE: bias+leaky+w5 dot
// accumulated into zacc[4] (rows g, g+8 of each tile) instead of storing.
template <int KP, int NW, int SS, int DS, bool FUSE>
__device__ __forceinline__ void run_pass(
    const __half* sA, __half* sD, char* ring,
    const float* __restrict__ bias, const float* __restrict__ w5,
    float* zacc, int ncol0, int chunk_col0,
    int& chunk, int wm, int lane, int tid)
{
    constexpr int N8 = NW / 8;
    const int g = lane >> 2, tq = lane & 3;

    float acc[2][N8][4];
#pragma unroll
    for (int t = 0; t < 2; ++t)
#pragma unroll
        for (int n = 0; n < N8; ++n)
#pragma unroll
            for (int q = 0; q < 4; ++q) acc[t][n][q] = 0.f;

    uint32_t abase[2];
#pragma unroll
    for (int t = 0; t < 2; ++t)
        abase[t] = (uint32_t)__cvta_generic_to_shared(
            sA + (wm * 32 + t * 16 + (lane & 15)) * SS + ((lane >> 4) << 3));

    const int wbase = (ncol0 - chunk_col0) * 4 + tq;   // 16B-group index base

#pragma unroll 1
    for (int cc = 0; cc < KP / 32; ++cc) {
        cp_wait<2>();
        __syncthreads();
        // Overwrites the slot of chunk-1: safe, all warps passed the barrier
        // above (so finished reading it last iteration / last pass).
        stage_chunk(chunk + 3, ring, tid);
        const char* slot = ring + (chunk & 3) * SLOT_BYTES;

        uint32_t a[2][2][4];
#pragma unroll
        for (int t = 0; t < 2; ++t)
#pragma unroll
            for (int kc = 0; kc < 2; ++kc)
                asm volatile("ldmatrix.sync.aligned.m8n8.x4.shared.b16 {%0,%1,%2,%3},[%4];\n"
                    : "=r"(a[t][kc][0]), "=r"(a[t][kc][1]), "=r"(a[t][kc][2]), "=r"(a[t][kc][3])
                    : "r"(abase[t] + (cc * 32 + kc * 16) * 2));

#pragma unroll
        for (int n8 = 0; n8 < N8; ++n8) {
            const uint4 w = *(const uint4*)(slot + ((wbase + (n8 * 8 + g) * 4) << 4));
#pragma unroll
            for (int t = 0; t < 2; ++t) {
                uint32_t d0 = 0, d1 = 0;                  // f16 partial over k=32
                mma_f16acc(d0, d1, a[t][0], w.x, w.y);
                mma_f16acc(d0, d1, a[t][1], w.z, w.w);
                const float2 f0 = __half22float2(*(__half2*)&d0);
                const float2 f1 = __half22float2(*(__half2*)&d1);
                acc[t][n8][0] += f0.x; acc[t][n8][1] += f0.y;
                acc[t][n8][2] += f1.x; acc[t][n8][3] += f1.y;
            }
        }
        ++chunk;
    }

#pragma unroll
    for (int t = 0; t < 2; ++t)
#pragma unroll
        for (int n8 = 0; n8 < N8; ++n8) {
            const int c0 = ncol0 + n8 * 8 + tq * 2;
            const float bb0 = bias[c0], bb1 = bias[c0 + 1];
            const float v0 = leaky(acc[t][n8][0] + bb0);
            const float v1 = leaky(acc[t][n8][1] + bb1);
            const float v2 = leaky(acc[t][n8][2] + bb0);
            const float v3 = leaky(acc[t][n8][3] + bb1);
            if (FUSE) {
                const float w50 = w5[c0], w51 = w5[c0 + 1];
                zacc[t * 2 + 0] += v0 * w50 + v1 * w51;   // row wm*32+t*16+g
                zacc[t * 2 + 1] += v2 * w50 + v3 * w51;   // row ... +8
            } else {
                const int r = wm * 32 + t * 16 + g;
                *(__half2*)(sD + r * DS + c0)       = __floats2half2_rn(v0, v1);
                *(__half2*)(sD + (r + 8) * DS + c0) = __floats2half2_rn(v2, v3);
            }
        }
}

// SMEM: activations 131072B + ring 65536B + zs/red 576B
#define SMEM_BYTES (128 * (40 + 72 + 136 + 264) * 2 + 4 * SLOT_BYTES + (128 + 16) * 4)

__global__ void __launch_bounds__(512, 1)
disc_kernel(const float* __restrict__ x, const float* __restrict__ lbl,
            const float* __restrict__ b1, const float* __restrict__ b2,
            const float* __restrict__ b3, const float* __restrict__ b4,
            const float* __restrict__ W5, const float* __restrict__ b5)
{
    extern __shared__ char smraw[];
    __half* xs = (__half*)smraw;              // [128][40]
    __half* h1 = xs + 128 * 40;               // [128][72]
    __half* h2 = h1 + 128 * 72;               // [128][136]
    __half* h3 = h2 + 128 * 136;              // [128][264]
    char*  ring = (char*)(h3 + 128 * 264);    // 4 x 16KB
    float* zs  = (float*)(ring + 4 * SLOT_BYTES);
    float* red = zs + 128;

    const int tid = threadIdx.x, wid = tid >> 5, lane = tid & 31;
    const int wm = wid >> 2, wn = wid & 3;
    const int P0 = blockIdx.x * BM;
    const int b  = P0 / HW_, s0 = P0 % HW_;   // BM | HW: no image straddle

    for (int i = tid; i < BM * 19; i += 512) {
        const int c = i >> 7, p = i & 127;
        xs[p * 40 + c] = __float2half_rn(x[(b * 19 + c) * HW_ + s0 + p]);
    }
    for (int i = tid; i < BM * 13; i += 512) {
        const int c = 19 + (i >> 7), p = i & 127;
        xs[p * 40 + c] = __float2half_rn(0.f);
    }
    if (tid < BM) zs[tid] = 0.f;

    stage_chunk(0, ring, tid);
    stage_chunk(1, ring, tid);
    stage_chunk(2, ring, tid);

    int chunk = 0;
    run_pass<32,  16, 40,  72,  false>(xs, h1, ring, b1, nullptr, nullptr, wn * 16, 0, chunk, wm, lane, tid);
    __syncthreads();
    run_pass<64,  32, 72,  136, false>(h1, h2, ring, b2, nullptr, nullptr, wn * 32, 0, chunk, wm, lane, tid);
    __syncthreads();
    run_pass<128, 64, 136, 264, false>(h2, h3, ring, b3, nullptr, nullptr, wn * 64, 0, chunk, wm, lane, tid);
    __syncthreads();

    float zacc[4] = {0.f, 0.f, 0.f, 0.f};
    run_pass<256, 64, 264, 1, true>(h3, nullptr, ring, b4, W5, zacc, wn * 64,       0,   chunk, wm, lane, tid);
    run_pass<256, 64, 264, 1, true>(h3, nullptr, ring, b4, W5, zacc, 256 + wn * 64, 256, chunk, wm, lane, tid);

#pragma unroll
    for (int q = 0; q < 4; ++q) {
        zacc[q] += __shfl_xor_sync(0xffffffffu, zacc[q], 1);
        zacc[q] += __shfl_xor_sync(0xffffffffu, zacc[q], 2);
    }
    if ((lane & 3) == 0) {
        const int g = lane >> 2;
#pragma unroll
        for (int q = 0; q < 4; ++q)
            atomicAdd(&zs[wm * 32 + (q >> 1) * 16 + (q & 1) * 8 + g], zacc[q]);
    }
    __syncthreads();

    if (tid < BM) {
        const float z = zs[tid] + b5[0];
        const float l = lbl[P0 + tid];
        float bce = fmaxf(z, 0.f) - z * l + log1pf(expf(-fabsf(z)));
#pragma unroll
        for (int o = 16; o > 0; o >>= 1) bce += __shfl_xor_sync(0xffffffffu, bce, o);
        if (lane == 0) red[wid] = bce;
    }
    __syncthreads();
    if (tid == 0) atomicAdd(&g_acc, (double)(red[0] + red[1] + red[2] + red[3]));
}

__global__ void fin_kernel(float* out) {
    out[0] = (float)(g_acc * (1.0 / (double)NPIX));
}

extern "C" void kernel_launch(void* const* d_in, const int* in_sizes, int n_in,
                              void* d_out, int out_size) {
    (void)in_sizes; (void)n_in; (void)out_size;
    const float* x   = (const float*)d_in[0];
    const float* lbl = (const float*)d_in[1];
    const float* W1  = (const float*)d_in[2];
    const float* b1  = (const float*)d_in[3];
    const float* W2  = (const float*)d_in[4];
    const float* b2  = (const float*)d_in[5];
    const float* W3  = (const float*)d_in[6];
    const float* b3  = (const float*)d_in[7];
    const float* W4  = (const float*)d_in[8];
    const float* b4  = (const float*)d_in[9];
    const float* W5  = (const float*)d_in[10];
    const float* b5  = (const float*)d_in[11];

    cudaFuncSetAttribute(disc_kernel, cudaFuncAttributeMaxDynamicSharedMemorySize, SMEM_BYTES);

    prep_kernel<<<512, 256>>>(W1, W2, W3, W4);
    disc_kernel<<<NPIX / BM, 512, SMEM_BYTES>>>(x, lbl, b1, b2, b3, b4, W5, b5);
    fin_kernel<<<1, 1>>>((float*)d_out);
}